// round 13
// baseline (speedup 1.0000x reference)
#include <cuda_runtime.h>
#include <cuda_bf16.h>
#include <cstdint>

// out[i,j,e] = W[e, pos] + b[e],  pos = clip(idxs[j]-idxs[i], -32, 32) + 32
// Persistent single-wave kernel: 592 blocks (4/SM x 148 SMs), each builds the
// 65x128 LUT (33 KB) + idxs cache (4 KB) in shared ONCE, then grid-strides
// over the flattened 33.5M-float4 output. Pure HBM-write-bound streaming.
// Inner loop unrolled x4 for store-MLP (4 independent STG.E.128 in flight).

#define MAX_GAP 32
#define NPOS    (2 * MAX_GAP + 1)   // 65
#define EDIM    128
#define E4      (EDIM / 4)          // 32 float4 per vector
#define SMAX    1024
#define GRID    592                 // 4 blocks/SM * 148 SMs = one full wave

__global__ __launch_bounds__(256)
void rpe2d_persistent(const int* __restrict__ idxs,
                      const float* __restrict__ W,   // (E, NPOS) row-major
                      const float* __restrict__ b,   // (E,)
                      float4* __restrict__ out,      // flattened (S*S*E4)
                      int S)
{
    __shared__ float4 T[NPOS * E4];   // 33.3 KB lookup table
    __shared__ int    idx_s[SMAX];    // 4 KB idxs cache

    const int tid = threadIdx.x;

    // Build lookup table once: T[p][e4] = { W[e+k][p] + b[e+k] }
    for (int t = tid; t < NPOS * E4; t += blockDim.x) {
        const int p  = t >> 5;
        const int e4 = t & 31;
        const int e  = e4 * 4;
        float4 v;
        v.x = W[(e + 0) * NPOS + p] + b[e + 0];
        v.y = W[(e + 1) * NPOS + p] + b[e + 1];
        v.z = W[(e + 2) * NPOS + p] + b[e + 2];
        v.w = W[(e + 3) * NPOS + p] + b[e + 3];
        T[t] = v;
    }
    for (int j = tid; j < S; j += blockDim.x) {
        idx_s[j] = idxs[j];
    }
    __syncthreads();

    // Uniform grid-stride over all output float4s.
    // Lanes 0-31 of a warp share (i,j) and cover e4=0..31: idxs reads
    // broadcast, T read is a conflict-free 512B row slice, store is a
    // perfectly coalesced 512B contiguous write.
    const unsigned total = (unsigned)S * (unsigned)S * E4;
    const unsigned gsz   = (unsigned)gridDim.x * blockDim.x;
    #pragma unroll 4
    for (unsigned f = blockIdx.x * blockDim.x + tid; f < total; f += gsz) {
        const unsigned e4 = f & 31;
        const unsigned je = f >> 5;          // = i*S + j
        const unsigned i  = je / (unsigned)S;
        const unsigned j  = je - i * (unsigned)S;
        int d = idx_s[j] - idx_s[i];
        d = min(max(d, -MAX_GAP), MAX_GAP) + MAX_GAP;
        __stcs(&out[f], T[(unsigned)d * E4 + e4]);
    }
}

extern "C" void kernel_launch(void* const* d_in, const int* in_sizes, int n_in,
                              void* d_out, int out_size) {
    const int*   idxs = (const int*)d_in[0];   // (B*S,) int32
    const float* W    = (const float*)d_in[1]; // (E, NPOS) fp32
    const float* b    = (const float*)d_in[2]; // (E,) fp32
    float4* out = (float4*)d_out;

    const int S = in_sizes[0];                 // B = 1
    rpe2d_persistent<<<GRID, 256>>>(idxs, W, b, out, S);
}